// round 10
// baseline (speedup 1.0000x reference)
#include <cuda_runtime.h>
#include <math.h>

#define HDIM 512
#define BSZ  128
#define TIN  256
#define MLEN 128
#define VOC  32
#define BH   (BSZ*HDIM)
#define B2H  (BSZ*2*HDIM)
#define NBLK 148
#define NTHR 512
#define SLW  68          // smem row width in floats (16B-aligned, conflict-free)

typedef unsigned long long u64;

// ---------------- device scratch ----------------
__device__ float g_y0[TIN*BH];
__device__ float g_enc[TIN*BH];
__device__ float g_q[MLEN*BH];
__device__ float g_rnn[MLEN*B2H];
__device__ float g_h0[MLEN*BH];
__device__ float g_h1[MLEN*BH];
__device__ int   g_tok[(MLEN+1)*BSZ];
__device__ unsigned g_arrive;
__device__ volatile unsigned g_release;

// ---------------- shared memory ----------------
struct SmSlice { float hs[32*SLW]; float ws[48*SLW]; };   // 8704 + 13056 = 21760 B
struct SmA { float q[HDIM]; float sc[TIN]; float red[16]; };
struct SmL { float hrow[HDIM]; float lg[VOC]; };
union SmAll {
    SmSlice sl[8];            // 174080 B
    u64 comb[7][64][32];      // 114688 B (aliases; used only after GEMMs complete)
    SmA a;
    SmL l;
};

// ---------------- helpers ----------------
__device__ __forceinline__ u64 fma2(u64 a, u64 b, u64 c)
{
    u64 d;
    asm("fma.rn.f32x2 %0, %1, %2, %3;" : "=l"(d) : "l"(a), "l"(b), "l"(c));
    return d;
}
__device__ __forceinline__ u64 add2(u64 a, u64 b)
{
    u64 d;
    asm("add.rn.f32x2 %0, %1, %2;" : "=l"(d) : "l"(a), "l"(b));
    return d;
}
__device__ __forceinline__ float red2(u64 a)
{
    float lo, hi;
    asm("mov.b64 {%0, %1}, %2;" : "=f"(lo), "=f"(hi) : "l"(a));
    return lo + hi;
}
__device__ __forceinline__ unsigned su32(const void* p)
{
    return (unsigned)__cvta_generic_to_shared(p);
}
__device__ __forceinline__ void cpa16(unsigned saddr, const float* gaddr)
{
    asm volatile("cp.async.cg.shared.global [%0], [%1], 16;"
                 :: "r"(saddr), "l"(gaddr) : "memory");
}
__device__ __forceinline__ void cpa_commit_wait()
{
    asm volatile("cp.async.commit_group;");
    asm volatile("cp.async.wait_group 0;" ::: "memory");
}
// named barrier for one 64-thread k-slice (ids 1..8)
__device__ __forceinline__ void barg(int slice)
{
    asm volatile("bar.sync %0, %1;" :: "r"(slice + 1), "r"(64) : "memory");
}

// ---------------- software grid barrier ----------------
__device__ __forceinline__ void gsync(unsigned &phase)
{
    __threadfence();
    __syncthreads();
    phase++;
    if (threadIdx.x == 0) {
        unsigned p = phase;
        unsigned old = atomicAdd(&g_arrive, 1u);
        if (old == p * (unsigned)NBLK - 1u) {
            g_release = p;
        } else {
            while (g_release < p) { }
        }
        __threadfence();
    }
    __syncthreads();
}

// ---------------- K-sliced GEMM accumulate (per 64-thread slice) ----------------
// Output tile: 32 rows x 16 cols x NG gates. Slice handles k in [kBase, kBase+Kh),
// processed in 64-wide chunks loaded via cp.async (single buffer).
// Thread t1 (0..63): cG = t1&7 (col pair base), rG = t1>>3 (4-row group).
// ws row layout: gate*16 + cc*8 + cG  <->  tile col cG*2+cc (conflict-free reads).
template<int NG>
__device__ __forceinline__ void gemm_slice(
    const float* __restrict__ A, int lda,
    const float* __restrict__ W, int ldw,
    int kBase, int Kh, int rowBase, int colBase,
    u64 (&a0)[2][4], u64 (&a1)[2][4], u64 (&a2)[2][4],
    SmSlice& sg, int slice)
{
    const int t1 = threadIdx.x & 63;
    const int cG = t1 & 7;
    const int rG = t1 >> 3;
    float* hs = sg.hs;
    float* ws = sg.ws;
    const unsigned hsB = su32(hs);
    const unsigned wsB = su32(ws);

    const int nch = Kh >> 6;
    for (int c = 0; c < nch; c++) {
        const int k0 = kBase + (c << 6);

        // fill hs: 32 rows x 64 k = 512 x 16B vecs, 8 per thread
        #pragma unroll
        for (int v = 0; v < 8; v++) {
            int vid = t1*8 + v;
            int row = vid >> 4;
            int kv  = (vid & 15) << 2;
            cpa16(hsB + (unsigned)(row*SLW + kv)*4u,
                  A + (size_t)(rowBase + row)*lda + k0 + kv);
        }
        // fill ws: NG*16 rows x 64 k
        if (NG == 3) {
            #pragma unroll
            for (int v = 0; v < 12; v++) {
                int vid = t1*12 + v;          // 0..767
                int wr  = vid >> 4;           // 0..47
                int kv  = (vid & 15) << 2;
                int gate = wr >> 4;
                int loc  = wr & 15;
                int cpos = ((loc & 7) << 1) | (loc >> 3);
                cpa16(wsB + (unsigned)(wr*SLW + kv)*4u,
                      W + (size_t)(gate*HDIM + colBase + cpos)*ldw + k0 + kv);
            }
        } else {
            #pragma unroll
            for (int v = 0; v < 4; v++) {
                int vid = t1*4 + v;           // 0..255
                int wr  = vid >> 4;           // 0..15
                int kv  = (vid & 15) << 2;
                int cpos = ((wr & 7) << 1) | (wr >> 3);
                cpa16(wsB + (unsigned)(wr*SLW + kv)*4u,
                      W + (size_t)(colBase + cpos)*ldw + k0 + kv);
            }
        }
        cpa_commit_wait();
        barg(slice);

        // compute 16 kk-steps of 4 k each
        #pragma unroll
        for (int kk = 0; kk < 64; kk += 4) {
            ulonglong2 w0a = *(const ulonglong2*)&ws[(0*16 + 0*8 + cG)*SLW + kk];
            ulonglong2 w0b = *(const ulonglong2*)&ws[(0*16 + 1*8 + cG)*SLW + kk];
            ulonglong2 w1a, w1b, w2a, w2b;
            if (NG >= 2) {
                w1a = *(const ulonglong2*)&ws[(1*16 + 0*8 + cG)*SLW + kk];
                w1b = *(const ulonglong2*)&ws[(1*16 + 1*8 + cG)*SLW + kk];
            }
            if (NG >= 3) {
                w2a = *(const ulonglong2*)&ws[(2*16 + 0*8 + cG)*SLW + kk];
                w2b = *(const ulonglong2*)&ws[(2*16 + 1*8 + cG)*SLW + kk];
            }
            #pragma unroll
            for (int i = 0; i < 4; i++) {
                ulonglong2 h = *(const ulonglong2*)&hs[(rG*4 + i)*SLW + kk];
                a0[0][i] = fma2(h.x, w0a.x, a0[0][i]);
                a0[0][i] = fma2(h.y, w0a.y, a0[0][i]);
                a0[1][i] = fma2(h.x, w0b.x, a0[1][i]);
                a0[1][i] = fma2(h.y, w0b.y, a0[1][i]);
                if (NG >= 2) {
                    a1[0][i] = fma2(h.x, w1a.x, a1[0][i]);
                    a1[0][i] = fma2(h.y, w1a.y, a1[0][i]);
                    a1[1][i] = fma2(h.x, w1b.x, a1[1][i]);
                    a1[1][i] = fma2(h.y, w1b.y, a1[1][i]);
                }
                if (NG >= 3) {
                    a2[0][i] = fma2(h.x, w2a.x, a2[0][i]);
                    a2[0][i] = fma2(h.y, w2a.y, a2[0][i]);
                    a2[1][i] = fma2(h.x, w2b.x, a2[1][i]);
                    a2[1][i] = fma2(h.y, w2b.y, a2[1][i]);
                }
            }
        }
        barg(slice);   // buffer safe to refill
    }
}

// ---------------- one GRU output tile: 32 rows x 16 cols (512 thr, 8-way k-split) ----------------
__device__ void gru_tile(const float* __restrict__ h_in,
                         const float* __restrict__ Whh,
                         const float* __restrict__ bhh,
                         const float* __restrict__ xin,
                         int ldx, int KIN,
                         const float* __restrict__ Wih,
                         const float* __restrict__ bih,
                         float* __restrict__ h_out,
                         int rowBase, int colBase, SmAll& sm)
{
    const int tid   = threadIdx.x;
    const int t1    = tid & 63;
    const int slice = tid >> 6;
    const int cG    = t1 & 7;
    const int rG    = t1 >> 3;

    u64 ar[2][4]  = {{0,0,0,0},{0,0,0,0}};
    u64 az[2][4]  = {{0,0,0,0},{0,0,0,0}};
    u64 ahn[2][4] = {{0,0,0,0},{0,0,0,0}};
    u64 ain[2][4] = {{0,0,0,0},{0,0,0,0}};

    if (h_in)
        gemm_slice<3>(h_in, HDIM, Whh, HDIM, slice*(HDIM/8), HDIM/8,
                      rowBase, colBase, ar, az, ahn, sm.sl[slice], slice);

    if (KIN >= 32) {
        const int Ks = KIN / 8;
        gemm_slice<3>(xin, ldx, Wih, KIN, slice*Ks, Ks,
                      rowBase, colBase, ar, az, ain, sm.sl[slice], slice);
    }

    __syncthreads();
    if (slice) {
        u64* d = sm.comb[slice-1][t1];
        #pragma unroll
        for (int cc = 0; cc < 2; cc++)
            #pragma unroll
            for (int i = 0; i < 4; i++) {
                d[cc*4 + i]      = ar[cc][i];
                d[8 + cc*4 + i]  = az[cc][i];
                d[16 + cc*4 + i] = ahn[cc][i];
                d[24 + cc*4 + i] = ain[cc][i];
            }
    }
    __syncthreads();
    if (slice == 0) {
        #pragma unroll
        for (int s = 0; s < 7; s++) {
            const u64* d = sm.comb[s][t1];
            #pragma unroll
            for (int cc = 0; cc < 2; cc++)
                #pragma unroll
                for (int i = 0; i < 4; i++) {
                    ar[cc][i]  = add2(ar[cc][i],  d[cc*4 + i]);
                    az[cc][i]  = add2(az[cc][i],  d[8 + cc*4 + i]);
                    ahn[cc][i] = add2(ahn[cc][i], d[16 + cc*4 + i]);
                    ain[cc][i] = add2(ain[cc][i], d[24 + cc*4 + i]);
                }
        }

        #pragma unroll
        for (int cc = 0; cc < 2; cc++) {
            const int col = colBase + cG*2 + cc;
            const float bhr = bhh[col], bhz = bhh[HDIM+col], bhn = bhh[2*HDIM+col];
            const float bir = bih[col], biz = bih[HDIM+col], bin = bih[2*HDIM+col];
            float wr0 = 0.f, wz0 = 0.f, wn0 = 0.f;
            if (KIN < 32) {   // tiny-input path (encoder layer0, KIN=2)
                // preload weights for this col (K small)
                // handled inside the row loop below via direct loads
            }
            #pragma unroll
            for (int i = 0; i < 4; i++) {
                const int row = rowBase + rG*4 + i;
                float xr = 0.f, xz = 0.f, xn = 0.f;
                if (KIN < 32) {
                    #pragma unroll 2
                    for (int k = 0; k < 2; k++) {
                        float wrk = Wih[(size_t)(0*HDIM + col)*KIN + k];
                        float wzk = Wih[(size_t)(1*HDIM + col)*KIN + k];
                        float wnk = Wih[(size_t)(2*HDIM + col)*KIN + k];
                        float xv  = xin[(size_t)row*ldx + k];
                        xr = fmaf(xv, wrk, xr);
                        xz = fmaf(xv, wzk, xz);
                        xn = fmaf(xv, wnk, xn);
                    }
                }
                float accr = red2(ar[cc][i]) + xr + bhr + bir;
                float accz = red2(az[cc][i]) + xz + bhz + biz;
                float hnv  = red2(ahn[cc][i]) + bhn;
                float inv  = red2(ain[cc][i]) + xn + bin;
                float r = 1.f / (1.f + expf(-accr));
                float z = 1.f / (1.f + expf(-accz));
                float n = tanhf(inv + r * hnv);
                float hp = h_in ? h_in[(size_t)row*HDIM + col] : 0.f;
                h_out[(size_t)row*HDIM + col] = (1.f - z) * n + z * hp;
            }
            (void)wr0; (void)wz0; (void)wn0;
        }
    }
    __syncthreads();
}

// ---------------- linear tile: out = A @ W.T + b (512 thr, 8-way k-split) ----------------
__device__ void linear_tile(const float* __restrict__ A,
                            const float* __restrict__ W,
                            const float* __restrict__ bias,
                            float* __restrict__ out,
                            int rowBase, int colBase, SmAll& sm)
{
    const int tid   = threadIdx.x;
    const int t1    = tid & 63;
    const int slice = tid >> 6;
    const int cG    = t1 & 7;
    const int rG    = t1 >> 3;

    u64 acc[2][4] = {{0,0,0,0},{0,0,0,0}};
    u64 d1[2][4]  = {{0,0,0,0},{0,0,0,0}};
    u64 d2[2][4]  = {{0,0,0,0},{0,0,0,0}};
    gemm_slice<1>(A, HDIM, W, HDIM, slice*(HDIM/8), HDIM/8,
                  rowBase, colBase, acc, d1, d2, sm.sl[slice], slice);

    __syncthreads();
    if (slice) {
        u64* d = sm.comb[slice-1][t1];
        #pragma unroll
        for (int cc = 0; cc < 2; cc++)
            #pragma unroll
            for (int i = 0; i < 4; i++) d[cc*4 + i] = acc[cc][i];
    }
    __syncthreads();
    if (slice == 0) {
        #pragma unroll
        for (int s = 0; s < 7; s++) {
            const u64* d = sm.comb[s][t1];
            #pragma unroll
            for (int cc = 0; cc < 2; cc++)
                #pragma unroll
                for (int i = 0; i < 4; i++)
                    acc[cc][i] = add2(acc[cc][i], d[cc*4 + i]);
        }
        #pragma unroll
        for (int cc = 0; cc < 2; cc++) {
            const int col = colBase + cG*2 + cc;
            float bb = bias[col];
            #pragma unroll
            for (int i = 0; i < 4; i++)
                out[(size_t)(rowBase + rG*4 + i)*HDIM + col] = red2(acc[cc][i]) + bb;
        }
    }
    __syncthreads();
}

// ---------------- attention for one batch row (512 threads) ----------------
__device__ void attn_row(int b, int t,
                         const float* __restrict__ query,
                         const float* __restrict__ enc,
                         const float* __restrict__ emb,
                         const int*   __restrict__ tokp,
                         float* __restrict__ rnn_in,
                         float* __restrict__ att_out,
                         SmA& sa)
{
    const int tid = threadIdx.x;
    const int warp = tid >> 5, lane = tid & 31;

    sa.q[tid] = query[(size_t)b*HDIM + tid];
    __syncthreads();

    const float* encb = enc + (size_t)b*HDIM;
    for (int tt = warp; tt < TIN; tt += 16) {
        const float* e = encb + (size_t)tt*BH;
        float s = 0.f;
        #pragma unroll
        for (int k = lane; k < HDIM; k += 32) s = fmaf(sa.q[k], e[k], s);
        #pragma unroll
        for (int o = 16; o; o >>= 1) s += __shfl_xor_sync(0xffffffffu, s, o);
        if (!lane) sa.sc[tt] = s;
    }
    __syncthreads();

    if (tid < 256) {
        float v = sa.sc[tid];
        float m = v;
        #pragma unroll
        for (int o = 16; o; o >>= 1) m = fmaxf(m, __shfl_xor_sync(0xffffffffu, m, o));
        if (!lane) sa.red[warp] = m;
    }
    __syncthreads();
    float gm = sa.red[0];
    #pragma unroll
    for (int i = 1; i < 8; i++) gm = fmaxf(gm, sa.red[i]);
    __syncthreads();
    if (tid < 256) {
        float v = sa.sc[tid];
        float e = expf(v - gm);
        float s = e;
        #pragma unroll
        for (int o = 16; o; o >>= 1) s += __shfl_xor_sync(0xffffffffu, s, o);
        if (!lane) sa.red[8 + warp] = s;
        sa.sc[tid] = e;
    }
    __syncthreads();
    float tot = 0.f;
    #pragma unroll
    for (int i = 0; i < 8; i++) tot += sa.red[8 + i];
    float inv_tot = 1.f / tot;
    if (tid < 256) {
        float w = sa.sc[tid] * inv_tot;
        sa.sc[tid] = w;
        att_out[(size_t)b*MLEN*TIN + (size_t)t*TIN + tid] = w;
    }
    __syncthreads();

    float c = 0.f;
    #pragma unroll 4
    for (int tt = 0; tt < TIN; tt++)
        c = fmaf(sa.sc[tt], encb[(size_t)tt*BH + tid], c);
    float* rb = rnn_in + (size_t)b*1024;
    rb[512 + tid] = c;

    const int tk = tokp[b];
    rb[tid] = emb[(size_t)tk*HDIM + tid];
    __syncthreads();
}

// ---------------- logits + argmax for one batch row (512 threads) ----------------
__device__ void logits_row(int b, int t,
                           const float* __restrict__ g1,
                           const float* __restrict__ outW,
                           const float* __restrict__ outb,
                           float* __restrict__ vec_out,
                           int* __restrict__ tok_next,
                           SmL& sl)
{
    const int tid = threadIdx.x;
    const int warp = tid >> 5, lane = tid & 31;

    sl.hrow[tid] = g1[(size_t)b*HDIM + tid];
    __syncthreads();

    for (int v = warp; v < VOC; v += 16) {
        const float* wrow = outW + (size_t)v*HDIM;
        float s = 0.f;
        #pragma unroll
        for (int k = lane; k < HDIM; k += 32) s = fmaf(sl.hrow[k], wrow[k], s);
        #pragma unroll
        for (int o = 16; o; o >>= 1) s += __shfl_xor_sync(0xffffffffu, s, o);
        if (!lane) {
            s += outb[v];
            sl.lg[v] = s;
            vec_out[(size_t)b*MLEN*VOC + (size_t)t*VOC + v] = s;
        }
    }
    __syncthreads();
    if (tid == 0) {
        int best = 0; float bv = sl.lg[0];
        #pragma unroll
        for (int v = 1; v < VOC; v++)
            if (sl.lg[v] > bv) { bv = sl.lg[v]; best = v; }
        tok_next[b] = best;
    }
    __syncthreads();
}

// ---------------- init kernel ----------------
__global__ void init_kernel()
{
    if (threadIdx.x == 0) { g_arrive = 0; g_release = 0; }
    g_tok[threadIdx.x] = 0;
}

// ---------------- persistent megakernel ----------------
__global__ void __launch_bounds__(NTHR, 1)
mega_kernel(const float* __restrict__ x,
            const float* __restrict__ emb,
            const float* __restrict__ eWih0, const float* __restrict__ eWhh0,
            const float* __restrict__ ebih0, const float* __restrict__ ebhh0,
            const float* __restrict__ eWih1, const float* __restrict__ eWhh1,
            const float* __restrict__ ebih1, const float* __restrict__ ebhh1,
            const float* __restrict__ dWih0, const float* __restrict__ dWhh0,
            const float* __restrict__ dbih0, const float* __restrict__ dbhh0,
            const float* __restrict__ dWih1, const float* __restrict__ dWhh1,
            const float* __restrict__ dbih1, const float* __restrict__ dbhh1,
            const float* __restrict__ qW,    const float* __restrict__ qb,
            const float* __restrict__ outW,  const float* __restrict__ outb,
            float* __restrict__ vec_out,
            float* __restrict__ hid_out,
            float* __restrict__ att_out)
{
    extern __shared__ unsigned char smraw[];
    SmAll& sm = *reinterpret_cast<SmAll*>(smraw);
    unsigned phase = 0;
    const int bid = blockIdx.x;

    // ---------- encoder: layer0[s] and layer1[s-1] pipelined ----------
    for (int s = 0; s <= TIN; s++) {
        for (int u = bid; u < 256; u += NBLK) {
            int tile = u & 127;
            int rowBase = (tile >> 5) * 32;
            int colBase = (tile & 31) * 16;
            if (u < 128) {
                if (s < TIN) {
                    const float* hprev = s ? (g_y0 + (size_t)(s-1)*BH) : nullptr;
                    gru_tile(hprev, eWhh0, ebhh0,
                             x + (size_t)s*2, TIN*2, 2, eWih0, ebih0,
                             g_y0 + (size_t)s*BH, rowBase, colBase, sm);
                }
            } else {
                if (s >= 1) {
                    int t = s - 1;
                    const float* hprev = t ? (g_enc + (size_t)(t-1)*BH) : nullptr;
                    gru_tile(hprev, eWhh1, ebhh1,
                             g_y0 + (size_t)t*BH, HDIM, HDIM, eWih1, ebih1,
                             g_enc + (size_t)t*BH, rowBase, colBase, sm);
                }
            }
        }
        gsync(phase);
    }

    // ---------- decoder ----------
    for (int u = bid; u < 128; u += NBLK) {
        int rowBase = (u >> 5) * 32;
        int colBase = (u & 31) * 16;
        linear_tile(g_enc + (size_t)(TIN-1)*BH, qW, qb, g_q, rowBase, colBase, sm);
    }
    gsync(phase);

    for (int t = 0; t < MLEN; t++) {
        const float* h0prev = t ? (g_h0 + (size_t)(t-1)*BH) : (g_y0  + (size_t)(TIN-1)*BH);
        const float* h1prev = t ? (g_h1 + (size_t)(t-1)*BH) : (g_enc + (size_t)(TIN-1)*BH);

        // Ph_b: attention -> rnn_in[t]
        for (int u = bid; u < BSZ; u += NBLK)
            attn_row(u, t, g_q + (size_t)t*BH, g_enc, emb,
                     g_tok + (size_t)t*BSZ, g_rnn + (size_t)t*B2H, att_out, sm.a);
        gsync(phase);

        // Ph_c: decoder gru0 (hidden K=512 + input K=1024)
        for (int u = bid; u < 128; u += NBLK) {
            int rowBase = (u >> 5) * 32;
            int colBase = (u & 31) * 16;
            gru_tile(h0prev, dWhh0, dbhh0,
                     g_rnn + (size_t)t*B2H, 2*HDIM, 2*HDIM, dWih0, dbih0,
                     g_h0 + (size_t)t*BH, rowBase, colBase, sm);
        }
        gsync(phase);

        // Ph_d: decoder gru1
        for (int u = bid; u < 128; u += NBLK) {
            int rowBase = (u >> 5) * 32;
            int colBase = (u & 31) * 16;
            gru_tile(h1prev, dWhh1, dbhh1,
                     g_h0 + (size_t)t*BH, HDIM, HDIM, dWih1, dbih1,
                     g_h1 + (size_t)t*BH, rowBase, colBase, sm);
        }
        gsync(phase);

        // Ph_e: logits+argmax (0..127) and next-step query (128..255)
        for (int u = bid; u < 256; u += NBLK) {
            if (u < 128) {
                logits_row(u, t, g_h1 + (size_t)t*BH, outW, outb,
                           vec_out, g_tok + (size_t)(t+1)*BSZ, sm.l);
            } else if (t + 1 < MLEN) {
                int tile = u - 128;
                int rowBase = (tile >> 5) * 32;
                int colBase = (tile & 31) * 16;
                linear_tile(g_h1 + (size_t)t*BH, qW, qb,
                            g_q + (size_t)(t+1)*BH, rowBase, colBase, sm);
            }
        }
        gsync(phase);
    }

    // ---------- final hidden copy ----------
    for (int i = bid*NTHR + threadIdx.x; i < BH; i += NBLK*NTHR) {
        hid_out[i]      = g_h0[(size_t)(MLEN-1)*BH + i];
        hid_out[BH + i] = g_h1[(size_t)(MLEN-1)*BH + i];
    }
}

// ---------------- host ----------------
extern "C" void kernel_launch(void* const* d_in, const int* in_sizes, int n_in,
                              void* d_out, int out_size)
{
    const float* x     = (const float*)d_in[0];
    const float* emb   = (const float*)d_in[1];
    const float* eWih0 = (const float*)d_in[2];
    const float* eWhh0 = (const float*)d_in[3];
    const float* ebih0 = (const float*)d_in[4];
    const float* ebhh0 = (const float*)d_in[5];
    const float* eWih1 = (const float*)d_in[6];
    const float* eWhh1 = (const float*)d_in[7];
    const float* ebih1 = (const float*)d_in[8];
    const float* ebhh1 = (const float*)d_in[9];
    const float* dWih0 = (const float*)d_in[10];
    const float* dWhh0 = (const float*)d_in[11];
    const float* dbih0 = (const float*)d_in[12];
    const float* dbhh0 = (const float*)d_in[13];
    const float* dWih1 = (const float*)d_in[14];
    const float* dWhh1 = (const float*)d_in[15];
    const float* dbih1 = (const float*)d_in[16];
    const float* dbhh1 = (const float*)d_in[17];
    const float* qW    = (const float*)d_in[18];
    const float* qb    = (const float*)d_in[19];
    const float* outW  = (const float*)d_in[20];
    const float* outb  = (const float*)d_in[21];

    float* out     = (float*)d_out;
    float* vec_out = out;
    float* hid_out = out + (size_t)BSZ*MLEN*VOC;
    float* att_out = hid_out + 2*BH;

    static int smem_set = 0;
    if (!smem_set) {
        cudaFuncSetAttribute(mega_kernel,
                             cudaFuncAttributeMaxDynamicSharedMemorySize,
                             (int)sizeof(SmAll));
        smem_set = 1;
    }

    init_kernel<<<1, BSZ>>>();
    mega_kernel<<<NBLK, NTHR, sizeof(SmAll)>>>(x, emb,
                                eWih0, eWhh0, ebih0, ebhh0,
                                eWih1, eWhh1, ebih1, ebhh1,
                                dWih0, dWhh0, dbih0, dbhh0,
                                dWih1, dWhh1, dbih1, dbhh1,
                                qW, qb, outW, outb,
                                vec_out, hid_out, att_out);
}

// round 11
// speedup vs baseline: 1.2662x; 1.2662x over previous
#include <cuda_runtime.h>
#include <math.h>

#define HDIM 512
#define BSZ  128
#define TIN  256
#define MLEN 128
#define VOC  32
#define BH   (BSZ*HDIM)
#define B2H  (BSZ*2*HDIM)
#define NBLK 148
#define NTHR 512
#define SLW  68          // smem row width in floats (272B = 17*16, 16B aligned)

typedef unsigned long long u64;

// ---------------- device scratch ----------------
__device__ float g_y0[TIN*BH];
__device__ float g_enc[TIN*BH];
__device__ float g_q[MLEN*BH];
__device__ float g_rnn[MLEN*B2H];
__device__ float g_h0[MLEN*BH];
__device__ float g_h1[MLEN*BH];
__device__ int   g_tok[(MLEN+1)*BSZ];
__device__ unsigned g_arrive;
__device__ volatile unsigned g_release;

// ---------------- shared memory ----------------
struct SmSlice { float hs[2][32][SLW]; float ws[2][48][SLW]; };  // 43520 B
struct SmA { float q[HDIM]; float sc[TIN]; float red[16]; };
struct SmL { float hrow[HDIM]; float lg[VOC]; };
union SmAll {
    SmSlice sl[4];            // 174080 B
    u64 comb[3][128][16];     // 49152 B (aliases; used only after GEMMs complete)
    SmA a;
    SmL l;
};

// ---------------- helpers ----------------
__device__ __forceinline__ u64 fma2(u64 a, u64 b, u64 c)
{
    u64 d;
    asm("fma.rn.f32x2 %0, %1, %2, %3;" : "=l"(d) : "l"(a), "l"(b), "l"(c));
    return d;
}
__device__ __forceinline__ u64 add2(u64 a, u64 b)
{
    u64 d;
    asm("add.rn.f32x2 %0, %1, %2;" : "=l"(d) : "l"(a), "l"(b));
    return d;
}
__device__ __forceinline__ float red2(u64 a)
{
    float lo, hi;
    asm("mov.b64 {%0, %1}, %2;" : "=f"(lo), "=f"(hi) : "l"(a));
    return lo + hi;
}
__device__ __forceinline__ unsigned su32(const void* p)
{
    return (unsigned)__cvta_generic_to_shared(p);
}
__device__ __forceinline__ void cpa16(unsigned saddr, const float* gaddr)
{
    asm volatile("cp.async.cg.shared.global [%0], [%1], 16;"
                 :: "r"(saddr), "l"(gaddr) : "memory");
}
// named barrier for one 128-thread k-slice (ids 1..4)
__device__ __forceinline__ void barg(int slice)
{
    asm volatile("bar.sync %0, %1;" :: "r"(slice + 1), "r"(128) : "memory");
}

// ---------------- software grid barrier ----------------
__device__ __forceinline__ void gsync(unsigned &phase)
{
    __threadfence();
    __syncthreads();
    phase++;
    if (threadIdx.x == 0) {
        unsigned p = phase;
        unsigned old = atomicAdd(&g_arrive, 1u);
        if (old == p * (unsigned)NBLK - 1u) {
            g_release = p;
        } else {
            while (g_release < p) { }
        }
        __threadfence();
    }
    __syncthreads();
}

// ---------------- pipelined K-major GEMM accumulate (per 128-thread k-slice) ----------------
// Output tile: 32 rows x 16 cols x NG gates. Slice handles k in [kBase, kBase+Kh),
// 64-wide chunks, double-buffered via cp.async (no register staging).
// Thread t1: cL = t1&15 (col), rG = t1>>4 (4-row group).
template<int NG>
__device__ __forceinline__ void gemm_pipe(
    const float* __restrict__ A, int lda,
    const float* __restrict__ W, int ldw,
    int kBase, int Kh, int rowBase, int colBase,
    u64 (&a0)[4], u64 (&a1)[4], u64 (&a2)[4],
    SmSlice& sg, int slice)
{
    const int t1 = threadIdx.x & 127;
    const int cL = t1 & 15;
    const int rG = t1 >> 4;
    const int nch = Kh >> 6;

    // fill one 64-k chunk into buffer `buf` via cp.async, then commit
#define FILL(buf, ch) do {                                                   \
        int k0_ = kBase + ((ch) << 6);                                       \
        _Pragma("unroll")                                                    \
        for (int v = 0; v < 4; v++) {                                        \
            int vid = t1*4 + v;                                              \
            int row = vid >> 4;                                              \
            int kv  = (vid & 15) << 2;                                       \
            cpa16(su32(&sg.hs[buf][row][kv]),                                \
                  A + (size_t)(rowBase + row)*lda + k0_ + kv);               \
        }                                                                    \
        if (NG == 3) {                                                       \
            _Pragma("unroll")                                                \
            for (int v = 0; v < 6; v++) {                                    \
                int vid = t1*6 + v;                                          \
                int wr  = vid >> 4;                                          \
                int kv  = (vid & 15) << 2;                                   \
                cpa16(su32(&sg.ws[buf][wr][kv]),                             \
                      W + (size_t)((wr>>4)*HDIM + colBase + (wr&15))*ldw     \
                        + k0_ + kv);                                         \
            }                                                                \
        } else {                                                             \
            _Pragma("unroll")                                                \
            for (int v = 0; v < 2; v++) {                                    \
                int vid = t1*2 + v;                                          \
                int wr  = vid >> 4;                                          \
                int kv  = (vid & 15) << 2;                                   \
                cpa16(su32(&sg.ws[buf][wr][kv]),                             \
                      W + (size_t)(colBase + wr)*ldw + k0_ + kv);            \
            }                                                                \
        }                                                                    \
        asm volatile("cp.async.commit_group;");                              \
    } while (0)

    FILL(0, 0);

    for (int c = 0; c < nch; c++) {
        const int cur = c & 1;
        if (c + 1 < nch) {
            FILL(cur ^ 1, c + 1);
            asm volatile("cp.async.wait_group 1;" ::: "memory");
        } else {
            asm volatile("cp.async.wait_group 0;" ::: "memory");
        }
        barg(slice);   // all threads' fills of buffer `cur` complete & visible

        #pragma unroll
        for (int kk = 0; kk < 64; kk += 4) {
            ulonglong2 w0 = *(const ulonglong2*)&sg.ws[cur][cL][kk];
            ulonglong2 w1, w2;
            if (NG >= 2) w1 = *(const ulonglong2*)&sg.ws[cur][16 + cL][kk];
            if (NG >= 3) w2 = *(const ulonglong2*)&sg.ws[cur][32 + cL][kk];
            #pragma unroll
            for (int i = 0; i < 4; i++) {
                ulonglong2 h = *(const ulonglong2*)&sg.hs[cur][rG*4 + i][kk];
                a0[i] = fma2(h.x, w0.x, a0[i]);
                a0[i] = fma2(h.y, w0.y, a0[i]);
                if (NG >= 2) { a1[i] = fma2(h.x, w1.x, a1[i]);
                               a1[i] = fma2(h.y, w1.y, a1[i]); }
                if (NG >= 3) { a2[i] = fma2(h.x, w2.x, a2[i]);
                               a2[i] = fma2(h.y, w2.y, a2[i]); }
            }
        }
        barg(slice);   // buffer `cur` safe to refill next iteration
    }
#undef FILL
}

// ---------------- one GRU output tile: 32 rows x 16 cols (512 thr, 4-way k-split) ----------------
__device__ void gru_tile(const float* __restrict__ h_in,
                         const float* __restrict__ Whh,
                         const float* __restrict__ bhh,
                         const float* __restrict__ xin,
                         int ldx, int KIN,
                         const float* __restrict__ Wih,
                         const float* __restrict__ bih,
                         float* __restrict__ h_out,
                         int rowBase, int colBase, SmAll& sm)
{
    const int tid   = threadIdx.x;
    const int t1    = tid & 127;
    const int slice = tid >> 7;
    const int cL    = t1 & 15;
    const int rG    = t1 >> 4;
    const int col   = colBase + cL;

    u64 ar[4] = {0,0,0,0}, az[4] = {0,0,0,0};
    u64 ahn[4] = {0,0,0,0}, ain[4] = {0,0,0,0};
    float xr[4] = {0.f,0.f,0.f,0.f}, xz[4] = {0.f,0.f,0.f,0.f}, xn[4] = {0.f,0.f,0.f,0.f};

    if (h_in)
        gemm_pipe<3>(h_in, HDIM, Whh, HDIM, slice*(HDIM/4), HDIM/4,
                     rowBase, colBase, ar, az, ahn, sm.sl[slice], slice);

    if (KIN >= 32) {
        const int Kq = KIN / 4;
        gemm_pipe<3>(xin, ldx, Wih, KIN, slice*Kq, Kq,
                     rowBase, colBase, ar, az, ain, sm.sl[slice], slice);
    } else if (slice == 0) {
        for (int k = 0; k < KIN; k++) {
            float wr = Wih[(size_t)(0*HDIM + col)*KIN + k];
            float wz = Wih[(size_t)(1*HDIM + col)*KIN + k];
            float wn = Wih[(size_t)(2*HDIM + col)*KIN + k];
            #pragma unroll
            for (int i = 0; i < 4; i++) {
                float xv = xin[(size_t)(rowBase + rG*4 + i)*ldx + k];
                xr[i] = fmaf(xv, wr, xr[i]);
                xz[i] = fmaf(xv, wz, xz[i]);
                xn[i] = fmaf(xv, wn, xn[i]);
            }
        }
    }

    __syncthreads();
    if (slice) {
        u64* d = sm.comb[slice-1][t1];
        #pragma unroll
        for (int i = 0; i < 4; i++) {
            d[i]      = ar[i];
            d[4 + i]  = az[i];
            d[8 + i]  = ahn[i];
            d[12 + i] = ain[i];
        }
    }
    __syncthreads();
    if (slice == 0) {
        #pragma unroll
        for (int s = 0; s < 3; s++) {
            const u64* d = sm.comb[s][t1];
            #pragma unroll
            for (int i = 0; i < 4; i++) {
                ar[i]  = add2(ar[i],  d[i]);
                az[i]  = add2(az[i],  d[4 + i]);
                ahn[i] = add2(ahn[i], d[8 + i]);
                ain[i] = add2(ain[i], d[12 + i]);
            }
        }

        const float bhr = bhh[col], bhz = bhh[HDIM+col], bhn = bhh[2*HDIM+col];
        const float bir = bih[col], biz = bih[HDIM+col], bin = bih[2*HDIM+col];

        #pragma unroll
        for (int i = 0; i < 4; i++) {
            int row = rowBase + rG*4 + i;
            float accr = red2(ar[i]) + xr[i] + bhr + bir;
            float accz = red2(az[i]) + xz[i] + bhz + biz;
            float hnv  = red2(ahn[i]) + bhn;
            float inv  = red2(ain[i]) + xn[i] + bin;
            float r = 1.f / (1.f + expf(-accr));
            float z = 1.f / (1.f + expf(-accz));
            float n = tanhf(inv + r * hnv);
            float hp = h_in ? h_in[(size_t)row*HDIM + col] : 0.f;
            h_out[(size_t)row*HDIM + col] = (1.f - z) * n + z * hp;
        }
    }
    __syncthreads();
}

// ---------------- linear tile: out = A @ W.T + b (512 thr, 4-way k-split) ----------------
__device__ void linear_tile(const float* __restrict__ A,
                            const float* __restrict__ W,
                            const float* __restrict__ bias,
                            float* __restrict__ out,
                            int rowBase, int colBase, SmAll& sm)
{
    const int tid   = threadIdx.x;
    const int t1    = tid & 127;
    const int slice = tid >> 7;
    const int cL    = t1 & 15;
    const int rG    = t1 >> 4;

    u64 acc[4] = {0,0,0,0}, d1[4] = {0,0,0,0}, d2[4] = {0,0,0,0};
    gemm_pipe<1>(A, HDIM, W, HDIM, slice*(HDIM/4), HDIM/4,
                 rowBase, colBase, acc, d1, d2, sm.sl[slice], slice);

    __syncthreads();
    if (slice) {
        u64* d = sm.comb[slice-1][t1];
        #pragma unroll
        for (int i = 0; i < 4; i++) d[i] = acc[i];
    }
    __syncthreads();
    if (slice == 0) {
        #pragma unroll
        for (int s = 0; s < 3; s++) {
            const u64* d = sm.comb[s][t1];
            #pragma unroll
            for (int i = 0; i < 4; i++) acc[i] = add2(acc[i], d[i]);
        }
        float bb = bias[colBase + cL];
        #pragma unroll
        for (int i = 0; i < 4; i++)
            out[(size_t)(rowBase + rG*4 + i)*HDIM + colBase + cL] = red2(acc[i]) + bb;
    }
    __syncthreads();
}

// ---------------- attention for one batch row (512 threads) ----------------
__device__ void attn_row(int b, int t,
                         const float* __restrict__ query,
                         const float* __restrict__ enc,
                         const float* __restrict__ emb,
                         const int*   __restrict__ tokp,
                         float* __restrict__ rnn_in,
                         float* __restrict__ att_out,
                         SmA& sa)
{
    const int tid = threadIdx.x;
    const int warp = tid >> 5, lane = tid & 31;

    sa.q[tid] = query[(size_t)b*HDIM + tid];
    __syncthreads();

    const float* encb = enc + (size_t)b*HDIM;
    for (int tt = warp; tt < TIN; tt += 16) {
        const float* e = encb + (size_t)tt*BH;
        float s = 0.f;
        #pragma unroll
        for (int k = lane; k < HDIM; k += 32) s = fmaf(sa.q[k], e[k], s);
        #pragma unroll
        for (int o = 16; o; o >>= 1) s += __shfl_xor_sync(0xffffffffu, s, o);
        if (!lane) sa.sc[tt] = s;
    }
    __syncthreads();

    if (tid < 256) {
        float v = sa.sc[tid];
        float m = v;
        #pragma unroll
        for (int o = 16; o; o >>= 1) m = fmaxf(m, __shfl_xor_sync(0xffffffffu, m, o));
        if (!lane) sa.red[warp] = m;
    }
    __syncthreads();
    float gm = sa.red[0];
    #pragma unroll
    for (int i = 1; i < 8; i++) gm = fmaxf(gm, sa.red[i]);
    __syncthreads();
    if (tid < 256) {
        float v = sa.sc[tid];
        float e = expf(v - gm);
        float s = e;
        #pragma unroll
        for (int o = 16; o; o >>= 1) s += __shfl_xor_sync(0xffffffffu, s, o);
        if (!lane) sa.red[8 + warp] = s;
        sa.sc[tid] = e;
    }
    __syncthreads();
    float tot = 0.f;
    #pragma unroll
    for (int i = 0; i < 8; i++) tot += sa.red[8 + i];
    float inv_tot = 1.f / tot;
    if (tid < 256) {
        float w = sa.sc[tid] * inv_tot;
        sa.sc[tid] = w;
        att_out[(size_t)b*MLEN*TIN + (size_t)t*TIN + tid] = w;
    }
    __syncthreads();

    float c = 0.f;
    #pragma unroll 4
    for (int tt = 0; tt < TIN; tt++)
        c = fmaf(sa.sc[tt], encb[(size_t)tt*BH + tid], c);
    float* rb = rnn_in + (size_t)b*1024;
    rb[512 + tid] = c;

    const int tk = tokp[b];
    rb[tid] = emb[(size_t)tk*HDIM + tid];
    __syncthreads();
}

// ---------------- logits + argmax for one batch row (512 threads) ----------------
__device__ void logits_row(int b, int t,
                           const float* __restrict__ g1,
                           const float* __restrict__ outW,
                           const float* __restrict__ outb,
                           float* __restrict__ vec_out,
                           int* __restrict__ tok_next,
                           SmL& sl)
{
    const int tid = threadIdx.x;
    const int warp = tid >> 5, lane = tid & 31;

    sl.hrow[tid] = g1[(size_t)b*HDIM + tid];
    __syncthreads();

    for (int v = warp; v < VOC; v += 16) {
        const float* wrow = outW + (size_t)v*HDIM;
        float s = 0.f;
        #pragma unroll
        for (int k = lane; k < HDIM; k += 32) s = fmaf(sl.hrow[k], wrow[k], s);
        #pragma unroll
        for (int o = 16; o; o >>= 1) s += __shfl_xor_sync(0xffffffffu, s, o);
        if (!lane) {
            s += outb[v];
            sl.lg[v] = s;
            vec_out[(size_t)b*MLEN*VOC + (size_t)t*VOC + v] = s;
        }
    }
    __syncthreads();
    if (tid == 0) {
        int best = 0; float bv = sl.lg[0];
        #pragma unroll
        for (int v = 1; v < VOC; v++)
            if (sl.lg[v] > bv) { bv = sl.lg[v]; best = v; }
        tok_next[b] = best;
    }
    __syncthreads();
}

// ---------------- init kernel ----------------
__global__ void init_kernel()
{
    if (threadIdx.x == 0) { g_arrive = 0; g_release = 0; }
    g_tok[threadIdx.x] = 0;
}

// ---------------- persistent megakernel ----------------
__global__ void __launch_bounds__(NTHR, 1)
mega_kernel(const float* __restrict__ x,
            const float* __restrict__ emb,
            const float* __restrict__ eWih0, const float* __restrict__ eWhh0,
            const float* __restrict__ ebih0, const float* __restrict__ ebhh0,
            const float* __restrict__ eWih1, const float* __restrict__ eWhh1,
            const float* __restrict__ ebih1, const float* __restrict__ ebhh1,
            const float* __restrict__ dWih0, const float* __restrict__ dWhh0,
            const float* __restrict__ dbih0, const float* __restrict__ dbhh0,
            const float* __restrict__ dWih1, const float* __restrict__ dWhh1,
            const float* __restrict__ dbih1, const float* __restrict__ dbhh1,
            const float* __restrict__ qW,    const float* __restrict__ qb,
            const float* __restrict__ outW,  const float* __restrict__ outb,
            float* __restrict__ vec_out,
            float* __restrict__ hid_out,
            float* __restrict__ att_out)
{
    extern __shared__ unsigned char smraw[];
    SmAll& sm = *reinterpret_cast<SmAll*>(smraw);
    unsigned phase = 0;
    const int bid = blockIdx.x;

    // ---------- encoder: layer0[s] and layer1[s-1] pipelined ----------
    for (int s = 0; s <= TIN; s++) {
        for (int u = bid; u < 256; u += NBLK) {
            int tile = u & 127;
            int rowBase = (tile >> 5) * 32;
            int colBase = (tile & 31) * 16;
            if (u < 128) {
                if (s < TIN) {
                    const float* hprev = s ? (g_y0 + (size_t)(s-1)*BH) : nullptr;
                    gru_tile(hprev, eWhh0, ebhh0,
                             x + (size_t)s*2, TIN*2, 2, eWih0, ebih0,
                             g_y0 + (size_t)s*BH, rowBase, colBase, sm);
                }
            } else {
                if (s >= 1) {
                    int t = s - 1;
                    const float* hprev = t ? (g_enc + (size_t)(t-1)*BH) : nullptr;
                    gru_tile(hprev, eWhh1, ebhh1,
                             g_y0 + (size_t)t*BH, HDIM, HDIM, eWih1, ebih1,
                             g_enc + (size_t)t*BH, rowBase, colBase, sm);
                }
            }
        }
        gsync(phase);
    }

    // ---------- decoder ----------
    for (int u = bid; u < 128; u += NBLK) {
        int rowBase = (u >> 5) * 32;
        int colBase = (u & 31) * 16;
        linear_tile(g_enc + (size_t)(TIN-1)*BH, qW, qb, g_q, rowBase, colBase, sm);
    }
    gsync(phase);

    for (int t = 0; t < MLEN; t++) {
        const float* h0prev = t ? (g_h0 + (size_t)(t-1)*BH) : (g_y0  + (size_t)(TIN-1)*BH);
        const float* h1prev = t ? (g_h1 + (size_t)(t-1)*BH) : (g_enc + (size_t)(TIN-1)*BH);

        // Ph_b: attention -> rnn_in[t]
        for (int u = bid; u < BSZ; u += NBLK)
            attn_row(u, t, g_q + (size_t)t*BH, g_enc, emb,
                     g_tok + (size_t)t*BSZ, g_rnn + (size_t)t*B2H, att_out, sm.a);
        gsync(phase);

        // Ph_c: decoder gru0 (hidden K=512 + input K=1024)
        for (int u = bid; u < 128; u += NBLK) {
            int rowBase = (u >> 5) * 32;
            int colBase = (u & 31) * 16;
            gru_tile(h0prev, dWhh0, dbhh0,
                     g_rnn + (size_t)t*B2H, 2*HDIM, 2*HDIM, dWih0, dbih0,
                     g_h0 + (size_t)t*BH, rowBase, colBase, sm);
        }
        gsync(phase);

        // Ph_d: decoder gru1
        for (int u = bid; u < 128; u += NBLK) {
            int rowBase = (u >> 5) * 32;
            int colBase = (u & 31) * 16;
            gru_tile(h1prev, dWhh1, dbhh1,
                     g_h0 + (size_t)t*BH, HDIM, HDIM, dWih1, dbih1,
                     g_h1 + (size_t)t*BH, rowBase, colBase, sm);
        }
        gsync(phase);

        // Ph_e: logits+argmax (0..127) and next-step query (128..255)
        for (int u = bid; u < 256; u += NBLK) {
            if (u < 128) {
                logits_row(u, t, g_h1 + (size_t)t*BH, outW, outb,
                           vec_out, g_tok + (size_t)(t+1)*BSZ, sm.l);
            } else if (t + 1 < MLEN) {
                int tile = u - 128;
                int rowBase = (tile >> 5) * 32;
                int colBase = (tile & 31) * 16;
                linear_tile(g_h1 + (size_t)t*BH, qW, qb,
                            g_q + (size_t)(t+1)*BH, rowBase, colBase, sm);
            }
        }
        gsync(phase);
    }

    // ---------- final hidden copy ----------
    for (int i = bid*NTHR + threadIdx.x; i < BH; i += NBLK*NTHR) {
        hid_out[i]      = g_h0[(size_t)(MLEN-1)*BH + i];
        hid_out[BH + i] = g_h1[(size_t)(MLEN-1)*BH + i];
    }
}

// ---------------- host ----------------
extern "C" void kernel_launch(void* const* d_in, const int* in_sizes, int n_in,
                              void* d_out, int out_size)
{
    const float* x     = (const float*)d_in[0];
    const float* emb   = (const float*)d_in[1];
    const float* eWih0 = (const float*)d_in[2];
    const float* eWhh0 = (const float*)d_in[3];
    const float* ebih0 = (const float*)d_in[4];
    const float* ebhh0 = (const float*)d_in[5];
    const float* eWih1 = (const float*)d_in[6];
    const float* eWhh1 = (const float*)d_in[7];
    const float* ebih1 = (const float*)d_in[8];
    const float* ebhh1 = (const float*)d_in[9];
    const float* dWih0 = (const float*)d_in[10];
    const float* dWhh0 = (const float*)d_in[11];
    const float* dbih0 = (const float*)d_in[12];
    const float* dbhh0 = (const float*)d_in[13];
    const float* dWih1 = (const float*)d_in[14];
    const float* dWhh1 = (const float*)d_in[15];
    const float* dbih1 = (const float*)d_in[16];
    const float* dbhh1 = (const float*)d_in[17];
    const float* qW    = (const float*)d_in[18];
    const float* qb    = (const float*)d_in[19];
    const float* outW  = (const float*)d_in[20];
    const float* outb  = (const float*)d_in[21];

    float* out     = (float*)d_out;
    float* vec_out = out;
    float* hid_out = out + (size_t)BSZ*MLEN*VOC;
    float* att_out = hid_out + 2*BH;

    static int smem_set = 0;
    if (!smem_set) {
        cudaFuncSetAttribute(mega_kernel,
                             cudaFuncAttributeMaxDynamicSharedMemorySize,
                             (int)sizeof(SmAll));
        smem_set = 1;
    }

    init_kernel<<<1, BSZ>>>();
    mega_kernel<<<NBLK, NTHR, sizeof(SmAll)>>>(x, emb,
                                eWih0, eWhh0, ebih0, ebhh0,
                                eWih1, eWhh1, ebih1, ebhh1,
                                dWih0, dWhh0, dbih0, dbhh0,
                                dWih1, dWhh1, dbih1, dbhh1,
                                qW, qb, outW, outb,
                                vec_out, hid_out, att_out);
}

// round 12
// speedup vs baseline: 1.2736x; 1.0058x over previous
#include <cuda_runtime.h>
#include <math.h>

#define HDIM 512
#define BSZ  128
#define TIN  256
#define MLEN 128
#define VOC  32
#define BH   (BSZ*HDIM)
#define B2H  (BSZ*2*HDIM)
#define NBLK 148
#define NTHR 512
#define SLW  68          // smem row width in floats (272B = 17*16, 16B aligned)

typedef unsigned long long u64;

// ---------------- device scratch ----------------
__device__ float g_y0[TIN*BH];
__device__ float g_enc[TIN*BH];
__device__ float g_q[MLEN*BH];
__device__ float g_rnn[MLEN*B2H];
__device__ float g_h0[MLEN*BH];
__device__ float g_h1[MLEN*BH];
__device__ int   g_tok[(MLEN+1)*BSZ];
__device__ unsigned g_arrive;
__device__ volatile unsigned g_release;

// ---------------- shared memory ----------------
struct SmSlice { float hs[2][32][SLW]; float ws[2][48][SLW]; };  // 43520 B
struct SmA { float q[HDIM]; float sc[TIN]; float red[16]; };
struct SmL { float hrow[HDIM]; float lg[VOC]; };
union SmAll {
    SmSlice sl[4];            // 174080 B
    u64 comb[3][128][16];     // 49152 B (aliases; used only after GEMMs complete)
    SmA a;
    SmL l;
};

// ---------------- helpers ----------------
__device__ __forceinline__ u64 fma2(u64 a, u64 b, u64 c)
{
    u64 d;
    asm("fma.rn.f32x2 %0, %1, %2, %3;" : "=l"(d) : "l"(a), "l"(b), "l"(c));
    return d;
}
__device__ __forceinline__ u64 add2(u64 a, u64 b)
{
    u64 d;
    asm("add.rn.f32x2 %0, %1, %2;" : "=l"(d) : "l"(a), "l"(b));
    return d;
}
__device__ __forceinline__ float red2(u64 a)
{
    float lo, hi;
    asm("mov.b64 {%0, %1}, %2;" : "=f"(lo), "=f"(hi) : "l"(a));
    return lo + hi;
}
__device__ __forceinline__ unsigned su32(const void* p)
{
    return (unsigned)__cvta_generic_to_shared(p);
}
__device__ __forceinline__ void cpa16(unsigned saddr, const float* gaddr)
{
    asm volatile("cp.async.cg.shared.global [%0], [%1], 16;"
                 :: "r"(saddr), "l"(gaddr) : "memory");
}
// named barrier for one 128-thread k-slice (ids 1..4)
__device__ __forceinline__ void barg(int slice)
{
    asm volatile("bar.sync %0, %1;" :: "r"(slice + 1), "r"(128) : "memory");
}

// ---------------- software grid barrier ----------------
__device__ __forceinline__ void gsync(unsigned &phase)
{
    __threadfence();
    __syncthreads();
    phase++;
    if (threadIdx.x == 0) {
        unsigned p = phase;
        unsigned old = atomicAdd(&g_arrive, 1u);
        if (old == p * (unsigned)NBLK - 1u) {
            g_release = p;
        } else {
            while (g_release < p) { }
        }
        __threadfence();
    }
    __syncthreads();
}

// ---------------- pipelined K-major GEMM accumulate (per 128-thread k-slice) ----------------
// Output tile: 32 rows x 16 cols x NG gates. Slice handles k in [kBase, kBase+Kh),
// 64-wide chunks, double-buffered via cp.async (no register staging).
// Thread t1: cL = t1&15 (col), rG = t1>>4 (4-row group).
template<int NG>
__device__ __forceinline__ void gemm_pipe(
    const float* __restrict__ A, int lda,
    const float* __restrict__ W, int ldw,
    int kBase, int Kh, int rowBase, int colBase,
    u64 (&a0)[4], u64 (&a1)[4], u64 (&a2)[4],
    SmSlice& sg, int slice)
{
    const int t1 = threadIdx.x & 127;
    const int cL = t1 & 15;
    const int rG = t1 >> 4;
    const int nch = Kh >> 6;

    // fill one 64-k chunk into buffer `buf` via cp.async, then commit
#define FILL(buf, ch) do {                                                   \
        int k0_ = kBase + ((ch) << 6);                                       \
        _Pragma("unroll")                                                    \
        for (int v = 0; v < 4; v++) {                                        \
            int vid = t1*4 + v;                                              \
            int row = vid >> 4;                                              \
            int kv  = (vid & 15) << 2;                                       \
            cpa16(su32(&sg.hs[buf][row][kv]),                                \
                  A + (size_t)(rowBase + row)*lda + k0_ + kv);               \
        }                                                                    \
        if (NG == 3) {                                                       \
            _Pragma("unroll")                                                \
            for (int v = 0; v < 6; v++) {                                    \
                int vid = t1*6 + v;                                          \
                int wr  = vid >> 4;                                          \
                int kv  = (vid & 15) << 2;                                   \
                cpa16(su32(&sg.ws[buf][wr][kv]),                             \
                      W + (size_t)((wr>>4)*HDIM + colBase + (wr&15))*ldw     \
                        + k0_ + kv);                                         \
            }                                                                \
        } else {                                                             \
            _Pragma("unroll")                                                \
            for (int v = 0; v < 2; v++) {                                    \
                int vid = t1*2 + v;                                          \
                int wr  = vid >> 4;                                          \
                int kv  = (vid & 15) << 2;                                   \
                cpa16(su32(&sg.ws[buf][wr][kv]),                             \
                      W + (size_t)(colBase + wr)*ldw + k0_ + kv);            \
            }                                                                \
        }                                                                    \
        asm volatile("cp.async.commit_group;");                              \
    } while (0)

    FILL(0, 0);

    for (int c = 0; c < nch; c++) {
        const int cur = c & 1;
        if (c + 1 < nch) {
            FILL(cur ^ 1, c + 1);
            asm volatile("cp.async.wait_group 1;" ::: "memory");
        } else {
            asm volatile("cp.async.wait_group 0;" ::: "memory");
        }
        barg(slice);   // all threads' fills of buffer `cur` complete & visible

        #pragma unroll
        for (int kk = 0; kk < 64; kk += 4) {
            ulonglong2 w0 = *(const ulonglong2*)&sg.ws[cur][cL][kk];
            ulonglong2 w1, w2;
            if (NG >= 2) w1 = *(const ulonglong2*)&sg.ws[cur][16 + cL][kk];
            if (NG >= 3) w2 = *(const ulonglong2*)&sg.ws[cur][32 + cL][kk];
            #pragma unroll
            for (int i = 0; i < 4; i++) {
                ulonglong2 h = *(const ulonglong2*)&sg.hs[cur][rG*4 + i][kk];
                a0[i] = fma2(h.x, w0.x, a0[i]);
                a0[i] = fma2(h.y, w0.y, a0[i]);
                if (NG >= 2) { a1[i] = fma2(h.x, w1.x, a1[i]);
                               a1[i] = fma2(h.y, w1.y, a1[i]); }
                if (NG >= 3) { a2[i] = fma2(h.x, w2.x, a2[i]);
                               a2[i] = fma2(h.y, w2.y, a2[i]); }
            }
        }
        barg(slice);   // buffer `cur` safe to refill next iteration
    }
#undef FILL
}

// ---------------- one GRU output tile: 32 rows x 16 cols (512 thr, 4-way k-split) ----------------
__device__ void gru_tile(const float* __restrict__ h_in,
                         const float* __restrict__ Whh,
                         const float* __restrict__ bhh,
                         const float* __restrict__ xin,
                         int ldx, int KIN,
                         const float* __restrict__ Wih,
                         const float* __restrict__ bih,
                         float* __restrict__ h_out,
                         int rowBase, int colBase, SmAll& sm)
{
    const int tid   = threadIdx.x;
    const int t1    = tid & 127;
    const int slice = tid >> 7;
    const int cL    = t1 & 15;
    const int rG    = t1 >> 4;
    const int col   = colBase + cL;

    u64 ar[4] = {0,0,0,0}, az[4] = {0,0,0,0};
    u64 ahn[4] = {0,0,0,0}, ain[4] = {0,0,0,0};
    float xr[4] = {0.f,0.f,0.f,0.f}, xz[4] = {0.f,0.f,0.f,0.f}, xn[4] = {0.f,0.f,0.f,0.f};

    if (h_in)
        gemm_pipe<3>(h_in, HDIM, Whh, HDIM, slice*(HDIM/4), HDIM/4,
                     rowBase, colBase, ar, az, ahn, sm.sl[slice], slice);

    if (KIN >= 32) {
        const int Kq = KIN / 4;
        gemm_pipe<3>(xin, ldx, Wih, KIN, slice*Kq, Kq,
                     rowBase, colBase, ar, az, ain, sm.sl[slice], slice);
    } else if (slice == 0) {
        for (int k = 0; k < KIN; k++) {
            float wr = Wih[(size_t)(0*HDIM + col)*KIN + k];
            float wz = Wih[(size_t)(1*HDIM + col)*KIN + k];
            float wn = Wih[(size_t)(2*HDIM + col)*KIN + k];
            #pragma unroll
            for (int i = 0; i < 4; i++) {
                float xv = xin[(size_t)(rowBase + rG*4 + i)*ldx + k];
                xr[i] = fmaf(xv, wr, xr[i]);
                xz[i] = fmaf(xv, wz, xz[i]);
                xn[i] = fmaf(xv, wn, xn[i]);
            }
        }
    }

    __syncthreads();
    if (slice) {
        u64* d = sm.comb[slice-1][t1];
        #pragma unroll
        for (int i = 0; i < 4; i++) {
            d[i]      = ar[i];
            d[4 + i]  = az[i];
            d[8 + i]  = ahn[i];
            d[12 + i] = ain[i];
        }
    }
    __syncthreads();
    if (slice == 0) {
        #pragma unroll
        for (int s = 0; s < 3; s++) {
            const u64* d = sm.comb[s][t1];
            #pragma unroll
            for (int i = 0; i < 4; i++) {
                ar[i]  = add2(ar[i],  d[i]);
                az[i]  = add2(az[i],  d[4 + i]);
                ahn[i] = add2(ahn[i], d[8 + i]);
                ain[i] = add2(ain[i], d[12 + i]);
            }
        }

        const float bhr = bhh[col], bhz = bhh[HDIM+col], bhn = bhh[2*HDIM+col];
        const float bir = bih[col], biz = bih[HDIM+col], bin = bih[2*HDIM+col];

        #pragma unroll
        for (int i = 0; i < 4; i++) {
            int row = rowBase + rG*4 + i;
            float accr = red2(ar[i]) + xr[i] + bhr + bir;
            float accz = red2(az[i]) + xz[i] + bhz + biz;
            float hnv  = red2(ahn[i]) + bhn;
            float inv  = red2(ain[i]) + xn[i] + bin;
            float r = 1.f / (1.f + expf(-accr));
            float z = 1.f / (1.f + expf(-accz));
            float n = tanhf(inv + r * hnv);
            float hp = h_in ? h_in[(size_t)row*HDIM + col] : 0.f;
            h_out[(size_t)row*HDIM + col] = (1.f - z) * n + z * hp;
        }
    }
    __syncthreads();
}

// ---------------- linear tile: out = A @ W.T + b (512 thr, 4-way k-split) ----------------
__device__ void linear_tile(const float* __restrict__ A,
                            const float* __restrict__ W,
                            const float* __restrict__ bias,
                            float* __restrict__ out,
                            int rowBase, int colBase, SmAll& sm)
{
    const int tid   = threadIdx.x;
    const int t1    = tid & 127;
    const int slice = tid >> 7;
    const int cL    = t1 & 15;
    const int rG    = t1 >> 4;

    u64 acc[4] = {0,0,0,0}, d1[4] = {0,0,0,0}, d2[4] = {0,0,0,0};
    gemm_pipe<1>(A, HDIM, W, HDIM, slice*(HDIM/4), HDIM/4,
                 rowBase, colBase, acc, d1, d2, sm.sl[slice], slice);

    __syncthreads();
    if (slice) {
        u64* d = sm.comb[slice-1][t1];
        #pragma unroll
        for (int i = 0; i < 4; i++) d[i] = acc[i];
    }
    __syncthreads();
    if (slice == 0) {
        #pragma unroll
        for (int s = 0; s < 3; s++) {
            const u64* d = sm.comb[s][t1];
            #pragma unroll
            for (int i = 0; i < 4; i++) acc[i] = add2(acc[i], d[i]);
        }
        float bb = bias[colBase + cL];
        #pragma unroll
        for (int i = 0; i < 4; i++)
            out[(size_t)(rowBase + rG*4 + i)*HDIM + colBase + cL] = red2(acc[i]) + bb;
    }
    __syncthreads();
}

// ---------------- attention for one batch row (512 threads) ----------------
__device__ void attn_row(int b, int t,
                         const float* __restrict__ query,
                         const float* __restrict__ enc,
                         const float* __restrict__ emb,
                         const int*   __restrict__ tokp,
                         float* __restrict__ rnn_in,
                         float* __restrict__ att_out,
                         SmA& sa)
{
    const int tid = threadIdx.x;
    const int warp = tid >> 5, lane = tid & 31;

    sa.q[tid] = query[(size_t)b*HDIM + tid];
    __syncthreads();

    const float* encb = enc + (size_t)b*HDIM;
    for (int tt = warp; tt < TIN; tt += 16) {
        const float* e = encb + (size_t)tt*BH;
        float s = 0.f;
        #pragma unroll
        for (int k = lane; k < HDIM; k += 32) s = fmaf(sa.q[k], e[k], s);
        #pragma unroll
        for (int o = 16; o; o >>= 1) s += __shfl_xor_sync(0xffffffffu, s, o);
        if (!lane) sa.sc[tt] = s;
    }
    __syncthreads();

    if (tid < 256) {
        float v = sa.sc[tid];
        float m = v;
        #pragma unroll
        for (int o = 16; o; o >>= 1) m = fmaxf(m, __shfl_xor_sync(0xffffffffu, m, o));
        if (!lane) sa.red[warp] = m;
    }
    __syncthreads();
    float gm = sa.red[0];
    #pragma unroll
    for (int i = 1; i < 8; i++) gm = fmaxf(gm, sa.red[i]);
    __syncthreads();
    if (tid < 256) {
        float v = sa.sc[tid];
        float e = expf(v - gm);
        float s = e;
        #pragma unroll
        for (int o = 16; o; o >>= 1) s += __shfl_xor_sync(0xffffffffu, s, o);
        if (!lane) sa.red[8 + warp] = s;
        sa.sc[tid] = e;
    }
    __syncthreads();
    float tot = 0.f;
    #pragma unroll
    for (int i = 0; i < 8; i++) tot += sa.red[8 + i];
    float inv_tot = 1.f / tot;
    if (tid < 256) {
        float w = sa.sc[tid] * inv_tot;
        sa.sc[tid] = w;
        att_out[(size_t)b*MLEN*TIN + (size_t)t*TIN + tid] = w;
    }
    __syncthreads();

    float c = 0.f;
    #pragma unroll 4
    for (int tt = 0; tt < TIN; tt++)
        c = fmaf(sa.sc[tt], encb[(size_t)tt*BH + tid], c);
    float* rb = rnn_in + (size_t)b*1024;
    rb[512 + tid] = c;

    const int tk = tokp[b];
    rb[tid] = emb[(size_t)tk*HDIM + tid];
    __syncthreads();
}

// ---------------- logits + argmax for one batch row (512 threads) ----------------
__device__ void logits_row(int b, int t,
                           const float* __restrict__ g1,
                           const float* __restrict__ outW,
                           const float* __restrict__ outb,
                           float* __restrict__ vec_out,
                           int* __restrict__ tok_next,
                           SmL& sl)
{
    const int tid = threadIdx.x;
    const int warp = tid >> 5, lane = tid & 31;

    sl.hrow[tid] = g1[(size_t)b*HDIM + tid];
    __syncthreads();

    for (int v = warp; v < VOC; v += 16) {
        const float* wrow = outW + (size_t)v*HDIM;
        float s = 0.f;
        #pragma unroll
        for (int k = lane; k < HDIM; k += 32) s = fmaf(sl.hrow[k], wrow[k], s);
        #pragma unroll
        for (int o = 16; o; o >>= 1) s += __shfl_xor_sync(0xffffffffu, s, o);
        if (!lane) {
            s += outb[v];
            sl.lg[v] = s;
            vec_out[(size_t)b*MLEN*VOC + (size_t)t*VOC + v] = s;
        }
    }
    __syncthreads();
    if (tid == 0) {
        int best = 0; float bv = sl.lg[0];
        #pragma unroll
        for (int v = 1; v < VOC; v++)
            if (sl.lg[v] > bv) { bv = sl.lg[v]; best = v; }
        tok_next[b] = best;
    }
    __syncthreads();
}

// ---------------- init kernel ----------------
__global__ void init_kernel()
{
    if (threadIdx.x == 0) { g_arrive = 0; g_release = 0; }
    g_tok[threadIdx.x] = 0;
}

// ---------------- persistent megakernel ----------------
__global__ void __launch_bounds__(NTHR, 1)
mega_kernel(const float* __restrict__ x,
            const float* __restrict__ emb,
            const float* __restrict__ eWih0, const float* __restrict__ eWhh0,
            const float* __restrict__ ebih0, const float* __restrict__ ebhh0,
            const float* __restrict__ eWih1, const float* __restrict__ eWhh1,
            const float* __restrict__ ebih1, const float* __restrict__ ebhh1,
            const float* __restrict__ dWih0, const float* __restrict__ dWhh0,
            const float* __restrict__ dbih0, const float* __restrict__ dbhh0,
            const float* __restrict__ dWih1, const float* __restrict__ dWhh1,
            const float* __restrict__ dbih1, const float* __restrict__ dbhh1,
            const float* __restrict__ qW,    const float* __restrict__ qb,
            const float* __restrict__ outW,  const float* __restrict__ outb,
            float* __restrict__ vec_out,
            float* __restrict__ hid_out,
            float* __restrict__ att_out)
{
    extern __shared__ unsigned char smraw[];
    SmAll& sm = *reinterpret_cast<SmAll*>(smraw);
    unsigned phase = 0;
    const int bid = blockIdx.x;

    // ---------- encoder: layer0[s] and layer1[s-1] pipelined ----------
    for (int s = 0; s <= TIN; s++) {
        for (int u = bid; u < 256; u += NBLK) {
            int tile = u & 127;
            int rowBase = (tile >> 5) * 32;
            int colBase = (tile & 31) * 16;
            if (u < 128) {
                if (s < TIN) {
                    const float* hprev = s ? (g_y0 + (size_t)(s-1)*BH) : nullptr;
                    gru_tile(hprev, eWhh0, ebhh0,
                             x + (size_t)s*2, TIN*2, 2, eWih0, ebih0,
                             g_y0 + (size_t)s*BH, rowBase, colBase, sm);
                }
            } else {
                if (s >= 1) {
                    int t = s - 1;
                    const float* hprev = t ? (g_enc + (size_t)(t-1)*BH) : nullptr;
                    gru_tile(hprev, eWhh1, ebhh1,
                             g_y0 + (size_t)t*BH, HDIM, HDIM, eWih1, ebih1,
                             g_enc + (size_t)t*BH, rowBase, colBase, sm);
                }
            }
        }
        gsync(phase);
    }

    // ---------- decoder ----------
    for (int u = bid; u < 128; u += NBLK) {
        int rowBase = (u >> 5) * 32;
        int colBase = (u & 31) * 16;
        linear_tile(g_enc + (size_t)(TIN-1)*BH, qW, qb, g_q, rowBase, colBase, sm);
    }
    gsync(phase);

    for (int t = 0; t < MLEN; t++) {
        const float* h0prev = t ? (g_h0 + (size_t)(t-1)*BH) : (g_y0  + (size_t)(TIN-1)*BH);
        const float* h1prev = t ? (g_h1 + (size_t)(t-1)*BH) : (g_enc + (size_t)(TIN-1)*BH);

        // Ph_b: attention -> rnn_in[t]
        for (int u = bid; u < BSZ; u += NBLK)
            attn_row(u, t, g_q + (size_t)t*BH, g_enc, emb,
                     g_tok + (size_t)t*BSZ, g_rnn + (size_t)t*B2H, att_out, sm.a);
        gsync(phase);

        // Ph_c: decoder gru0 (hidden K=512 + input K=1024)
        for (int u = bid; u < 128; u += NBLK) {
            int rowBase = (u >> 5) * 32;
            int colBase = (u & 31) * 16;
            gru_tile(h0prev, dWhh0, dbhh0,
                     g_rnn + (size_t)t*B2H, 2*HDIM, 2*HDIM, dWih0, dbih0,
                     g_h0 + (size_t)t*BH, rowBase, colBase, sm);
        }
        gsync(phase);

        // Ph_d: decoder gru1
        for (int u = bid; u < 128; u += NBLK) {
            int rowBase = (u >> 5) * 32;
            int colBase = (u & 31) * 16;
            gru_tile(h1prev, dWhh1, dbhh1,
                     g_h0 + (size_t)t*BH, HDIM, HDIM, dWih1, dbih1,
                     g_h1 + (size_t)t*BH, rowBase, colBase, sm);
        }
        gsync(phase);

        // Ph_e: logits+argmax (0..127) and next-step query (128..255)
        for (int u = bid; u < 256; u += NBLK) {
            if (u < 128) {
                logits_row(u, t, g_h1 + (size_t)t*BH, outW, outb,
                           vec_out, g_tok + (size_t)(t+1)*BSZ, sm.l);
            } else if (t + 1 < MLEN) {
                int tile = u - 128;
                int rowBase = (tile >> 5) * 32;
                int colBase = (tile & 31) * 16;
                linear_tile(g_h1 + (size_t)t*BH, qW, qb,
                            g_q + (size_t)(t+1)*BH, rowBase, colBase, sm);
            }
        }
        gsync(phase);
    }

    // ---------- final hidden copy ----------
    for (int i = bid*NTHR + threadIdx.x; i < BH; i += NBLK*NTHR) {
        hid_out[i]      = g_h0[(size_t)(MLEN-1)*BH + i];
        hid_out[BH + i] = g_h1[(size_t)(MLEN-1)*BH + i];
    }
}

// ---------------- host ----------------
extern "C" void kernel_launch(void* const* d_in, const int* in_sizes, int n_in,
                              void* d_out, int out_size)
{
    const float* x     = (const float*)d_in[0];
    const float* emb   = (const float*)d_in[1];
    const float* eWih0 = (const float*)d_in[2];
    const float* eWhh0 = (const float*)d_in[3];
    const float* ebih0 = (const float*)d_in[4];
    const float* ebhh0 = (const float*)d_in[5];
    const float* eWih1 = (const float*)d_in[6];
    const float* eWhh1 = (const float*)d_in[7];
    const float* ebih1 = (const float*)d_in[8];
    const float* ebhh1 = (const float*)d_in[9];
    const float* dWih0 = (const float*)d_in[10];
    const float* dWhh0 = (const float*)d_in[11];
    const float* dbih0 = (const float*)d_in[12];
    const float* dbhh0 = (const float*)d_in[13];
    const float* dWih1 = (const float*)d_in[14];
    const float* dWhh1 = (const float*)d_in[15];
    const float* dbih1 = (const float*)d_in[16];
    const float* dbhh1 = (const float*)d_in[17];
    const float* qW    = (const float*)d_in[18];
    const float* qb    = (const float*)d_in[19];
    const float* outW  = (const float*)d_in[20];
    const float* outb  = (const float*)d_in[21];

    float* out     = (float*)d_out;
    float* vec_out = out;
    float* hid_out = out + (size_t)BSZ*MLEN*VOC;
    float* att_out = hid_out + 2*BH;

    static int smem_set = 0;
    if (!smem_set) {
        cudaFuncSetAttribute(mega_kernel,
                             cudaFuncAttributeMaxDynamicSharedMemorySize,
                             (int)sizeof(SmAll));
        smem_set = 1;
    }

    init_kernel<<<1, BSZ>>>();
    mega_kernel<<<NBLK, NTHR, sizeof(SmAll)>>>(x, emb,
                                eWih0, eWhh0, ebih0, ebhh0,
                                eWih1, eWhh1, ebih1, ebhh1,
                                dWih0, dWhh0, dbih0, dbhh0,
                                dWih1, dWhh1, dbih1, dbhh1,
                                qW, qb, outW, outb,
                                vec_out, hid_out, att_out);
}